// round 15
// baseline (speedup 1.0000x reference)
#include <cuda_runtime.h>
#include <cstdint>
#include <cstddef>

#define FULLMASK 0xffffffffu

#define B_   16
#define N_   8192
#define CIN  64
#define CTOT 67
#define M_   1024
#define KK   32
#define HID  64
#define OUTC 128
#define SPAT (M_*KK)
#define NBLK (SPAT/64)      // 512 conv2 tiles per batch (64 spatial each)
#define NT1  128            // conv1 tiles per batch (256 spatial each)
#define KNNB 8              // knn blocks per batch (16*8+16 = 144 blocks: ONE wave)
#define EPSV 1e-5f

typedef unsigned long long ull;

// ---------------- device scratch (static, no allocation) ----------------
__device__ int   g_knn[B_*M_*KK];                       // 2 MB
__device__ float g_x1[(size_t)B_*HID*SPAT];             // 134 MB
__device__ float g_p1[B_*HID*NT1*2];                    // 1 MB
__device__ float g_p2[B_*OUTC*NBLK*2];                  // 8 MB
__device__ float g_mx2[(size_t)B_*M_*OUTC];             // 8 MB
__device__ float g_mn2[(size_t)B_*M_*OUTC];             // 8 MB
__device__ float g_cs1[B_*HID*2];
__device__ float g_cs2[B_*OUTC*2];
__device__ float g_centfb[B_*M_*3];
__device__ unsigned g_prog[B_*32];                      // 128B-padded per batch
__device__ float g_w1t[CTOT*64];                        // transposed weights [cin][cout]
__device__ float g_w2t[HID*OUTC];
__device__ int   g_dummy;

// ---------------- packed f32x2 helpers ----------------
__device__ __forceinline__ ull pack2(float lo, float hi) {
    ull r;
    asm("mov.b64 %0, {%1, %2};" : "=l"(r)
        : "r"(__float_as_uint(lo)), "r"(__float_as_uint(hi)));
    return r;
}
__device__ __forceinline__ void unpack2(ull v, float& lo, float& hi) {
    unsigned a, b;
    asm("mov.b64 {%0, %1}, %2;" : "=r"(a), "=r"(b) : "l"(v));
    lo = __uint_as_float(a); hi = __uint_as_float(b);
}
__device__ __forceinline__ ull add2(ull a, ull b) {
    ull r; asm("add.rn.f32x2 %0, %1, %2;" : "=l"(r) : "l"(a), "l"(b)); return r;
}
__device__ __forceinline__ ull mul2(ull a, ull b) {
    ull r; asm("mul.rn.f32x2 %0, %1, %2;" : "=l"(r) : "l"(a), "l"(b)); return r;
}
__device__ __forceinline__ ull fma2(ull a, ull b, ull c) {
    ull r; asm("fma.rn.f32x2 %0, %1, %2, %3;" : "=l"(r) : "l"(a), "l"(b), "l"(c)); return r;
}

// ---------------- reduction helpers ----------------
__device__ __forceinline__ unsigned redux_max_u32(unsigned v) {
    unsigned r;
    asm volatile("redux.sync.max.u32 %0, %1, 0xffffffff;" : "=r"(r) : "r"(v));
    return r;
}
__device__ __forceinline__ unsigned redux_min_u32(unsigned v) {
    unsigned r;
    asm volatile("redux.sync.min.u32 %0, %1, 0xffffffff;" : "=r"(r) : "r"(v));
    return r;
}
__device__ __forceinline__ int redux_max_s32(int v) {
    int r;
    asm volatile("redux.sync.max.s32 %0, %1, 0xffffffff;" : "=r"(r) : "r"(v));
    return r;
}

__device__ __forceinline__ unsigned f2key(float f) {
    unsigned u = __float_as_uint(f);
    unsigned mask = ((unsigned)((int)u >> 31)) | 0x80000000u;
    return u ^ mask;
}

__device__ __forceinline__ float2 blk_reduce2(float s, float s2) {
    const int lane = threadIdx.x & 31, w = threadIdx.x >> 5;
    #pragma unroll
    for (int o = 16; o; o >>= 1) {
        s  += __shfl_down_sync(FULLMASK, s,  o);
        s2 += __shfl_down_sync(FULLMASK, s2, o);
    }
    __shared__ float rs[8], rq[8];
    if (lane == 0) { rs[w] = s; rq[w] = s2; }
    __syncthreads();
    if (w == 0) {
        s  = (lane < 8) ? rs[lane] : 0.f;
        s2 = (lane < 8) ? rq[lane] : 0.f;
        #pragma unroll
        for (int o = 4; o; o >>= 1) {
            s  += __shfl_down_sync(FULLMASK, s,  o);
            s2 += __shfl_down_sync(FULLMASK, s2, o);
        }
    }
    return make_float2(s, s2);
}

// ---------------- progress handshake (padded counters + backoff) ------------
__device__ __forceinline__ void publish_prog(int b, unsigned v) {
    asm volatile("st.release.gpu.global.u32 [%0], %1;"
                 :: "l"(&g_prog[b * 32]), "r"(v) : "memory");
}
__device__ __forceinline__ void wait_prog(int b, unsigned need) {
    const int lane = threadIdx.x & 31;
    if (lane == 0) {
        unsigned got;
        for (;;) {
            asm volatile("ld.acquire.gpu.global.u32 %0, [%1];"
                         : "=r"(got) : "l"(&g_prog[b * 32]) : "memory");
            if (got >= need) break;
            __nanosleep((need - got > 16) ? 4000 : 300);
        }
    }
    __syncwarp();
}

// ---------------- K0: weight transpose prep (+dummy) ----------------
__global__ void wprep_kernel(const float* __restrict__ w1,
                             const float* __restrict__ w2) {
    const int t = blockIdx.x * 256 + threadIdx.x;
    if (t < CTOT * 64) {
        int cin = t >> 6, c = t & 63;
        g_w1t[cin * 64 + c] = w1[c * CTOT + cin];
    }
    if (t < HID * OUTC) {
        int cin = t >> 7, c = t & 127;
        g_w2t[cin * OUTC + c] = w2[c * HID + cin];
    }
}
__global__ void dummy_kernel(int t) { if (threadIdx.x == 0) g_dummy = t; }

// ---------------- FPS body (blocks 0..15): 1024 thr, 8 pts/thread -----------
__device__ __forceinline__ void fps_body(float* sm, const float* __restrict__ xyz,
                                         float* __restrict__ cent, int b) {
    float* xs = sm; float* ys = sm + N_; float* zs = sm + 2 * N_;
    __shared__ unsigned swb[2][32];
    __shared__ unsigned swi[2][32];
    const int t = threadIdx.x, lane = t & 31, w = t >> 5;
    const float* base = xyz + (size_t)b * N_ * 3;
    for (int p = t; p < N_; p += 1024) {
        xs[p] = base[3 * p]; ys[p] = base[3 * p + 1]; zs[p] = base[3 * p + 2];
    }
    __syncthreads();

    ull px2[4], py2[4], pz2[4];
    float dist[8];
    #pragma unroll
    for (int j = 0; j < 4; j++) {
        const int p0 = t + (2 * j) * 1024, p1 = p0 + 1024;
        px2[j] = pack2(xs[p0], xs[p1]);
        py2[j] = pack2(ys[p0], ys[p1]);
        pz2[j] = pack2(zs[p0], zs[p1]);
        dist[2 * j] = 1e10f; dist[2 * j + 1] = 1e10f;
    }
    float cx = xs[0], cy = ys[0], cz = zs[0];
    if (t == 0) {
        size_t o = (size_t)b * M_ * 3;
        cent[o] = cx; cent[o + 1] = cy; cent[o + 2] = cz;
        publish_prog(b, 1u);
    }

    for (int it = 1; it < M_; ++it) {
        const ull ncx = pack2(-cx, -cx);   // p + (-c) == p - c exactly (IEEE)
        const ull ncy = pack2(-cy, -cy);
        const ull ncz = pack2(-cz, -cz);
        float mv = -1.f;
        #pragma unroll
        for (int j = 0; j < 4; j++) {
            ull dx = add2(px2[j], ncx);
            ull dy = add2(py2[j], ncy);
            ull dz = add2(pz2[j], ncz);
            ull d = add2(add2(mul2(dx, dx), mul2(dy, dy)), mul2(dz, dz));
            float d0, d1; unpack2(d, d0, d1);
            float n0 = fminf(dist[2 * j], d0);
            float n1 = fminf(dist[2 * j + 1], d1);
            dist[2 * j] = n0; dist[2 * j + 1] = n1;
            mv = fmaxf(mv, fmaxf(n0, n1));
        }
        // rescan descending -> smallest point index with dist == mv (jnp.argmax)
        unsigned mi = 0;
        #pragma unroll
        for (int k = 7; k >= 0; k--)
            if (dist[k] == mv) mi = (unsigned)(t + k * 1024);

        unsigned mb = __float_as_uint(mv);
        unsigned wm = redux_max_u32(mb);
        unsigned wi = redux_min_u32((mb == wm) ? mi : 0xFFFFFFFFu);
        const int pb = it & 1;
        if (lane == 0) { swb[pb][w] = wm; swi[pb][w] = wi; }
        __syncthreads();
        unsigned vb = swb[pb][lane];
        unsigned vi = swi[pb][lane];
        unsigned gm = redux_max_u32(vb);
        unsigned far = redux_min_u32((vb == gm) ? vi : 0xFFFFFFFFu);
        cx = xs[far]; cy = ys[far]; cz = zs[far];
        if (t == 0) {
            size_t o = ((size_t)b * M_ + it) * 3;
            cent[o] = cx; cent[o + 1] = cy; cent[o + 2] = cz;
            publish_prog(b, (unsigned)(it + 1));
        }
    }
}

// ---------------- kNN + conv1 body (blocks 16..143): 1024 thr, 32 warps -----
// Warp wg = cb*32 + w handles mi = wg + 256*i, i=0..3 (frontier-tracking).
// After each iteration's 32 scans + barrier, the block runs conv1 for its 32
// fresh centroids as 4 tiles of 8 m (256 spatial, 1024-thread FFMA2 GEMM).
__device__ __forceinline__ void knn_body(float* sm, const float* __restrict__ xyz,
                                         const float* __restrict__ cent,
                                         const float* __restrict__ feat,
                                         const float* __restrict__ b1, int idx) {
    float* xs = sm; float* ys = sm + N_; float* zs = sm + 2 * N_; float* xn = sm + 3 * N_;
    float* Ws1 = sm + 4 * N_;                  // CTOT*64 floats
    float* Xs  = Ws1 + CTOT * 64;              // CTOT*264 floats (also stats staging)
    __shared__ float scent[32][4];
    const int b = idx >> 3, cb = idx & 7;
    const int t = threadIdx.x, lane = t & 31, w = t >> 5;
    const int wg = cb * 32 + w;                 // 0..255
    const float* base = xyz + (size_t)b * N_ * 3;
    for (int p = t; p < N_; p += 1024) {
        float x = base[3 * p], y = base[3 * p + 1], z = base[3 * p + 2];
        xs[p] = x; ys[p] = y; zs[p] = z;
        xn[p] = x * x + y * y + z * z;
    }
    for (int i = t; i < CTOT * 64; i += 1024) Ws1[i] = g_w1t[i];
    __syncthreads();

    const int ty = t & 31, tx = t >> 5;          // GEMM: 1 cout-pair x 8 sp
    for (int i = 0; i < 4; ++i) {
        // ---- scan phase: each warp one centroid ----
        const int mi = wg + 256 * i;
        wait_prog(b, (unsigned)(mi + 1));
        size_t co = ((size_t)b * M_ + mi) * 3;
        float cx = __ldcg(cent + co);
        float cy = __ldcg(cent + co + 1);
        float cz = __ldcg(cent + co + 2);
        if (lane == 0) { scent[w][0] = cx; scent[w][1] = cy; scent[w][2] = cz; }
        float cn = cx * cx + cy * cy + cz * cz;

        unsigned valkey; int vidx;
        {
            int p = lane;
            float d = cn + xn[p] - 2.f * (cx * xs[p] + cy * ys[p] + cz * zs[p]);
            valkey = f2key(d);
            vidx = p;
        }
        unsigned thr = redux_max_u32(valkey);
        for (int c0 = 32; c0 < N_; c0 += 32) {
            int p = c0 + lane;
            float d = cn + xn[p] - 2.f * (cx * xs[p] + cy * ys[p] + cz * zs[p]);
            unsigned dk = f2key(d);
            unsigned pend = __ballot_sync(FULLMASK, dk < thr);
            while (pend) {
                int src = __ffs(pend) - 1;
                pend &= pend - 1;
                unsigned dkj = __shfl_sync(FULLMASK, dk, src);
                if (dkj < thr) {
                    int pj = c0 + src;
                    unsigned vmax = redux_max_u32(valkey);
                    int cand = (valkey == vmax) ? vidx : -1;
                    int victimidx = redux_max_s32(cand);
                    if (valkey == vmax && vidx == victimidx) { valkey = dkj; vidx = pj; }
                    thr = redux_max_u32(valkey);
                }
            }
        }
        g_knn[((size_t)b * M_ + mi) * KK + lane] = vidx;
        __syncthreads();    // all 32 warps done; knn + scent visible block-wide

        // ---- conv1 phase: 4 tiles of 8 m (256 spatial each) ----
        const int mbase = cb * 32 + 256 * i;
        #pragma unroll 1
        for (int tt = 0; tt < 4; tt++) {
            const int m0 = mbase + tt * 8;
            const int tb = m0 >> 3;              // tile index 0..127
            const int s0 = m0 * KK;
            {   // gather: 4 threads per point (16 floats each)
                const int r = t & 3, ps = t >> 2;
                const int s = s0 + ps, m = s >> 5, kk = s & 31;
                const int gidx = g_knn[((size_t)b * M_ + m) * KK + kk];
                const float* fp = feat + ((size_t)b * N_ + gidx) * CIN + r * 16;
                #pragma unroll
                for (int q = 0; q < 4; q++) {
                    float4 v = *(const float4*)(fp + q * 4);
                    int row = 3 + r * 16 + q * 4;
                    Xs[(row + 0) * 264 + ps] = v.x;
                    Xs[(row + 1) * 264 + ps] = v.y;
                    Xs[(row + 2) * 264 + ps] = v.z;
                    Xs[(row + 3) * 264 + ps] = v.w;
                }
                if (r == 0) {
                    const int lw = m - mbase;
                    Xs[0 * 264 + ps] = xs[gidx] - scent[lw][0];
                    Xs[1 * 264 + ps] = ys[gidx] - scent[lw][1];
                    Xs[2 * 264 + ps] = zs[gidx] - scent[lw][2];
                }
            }
            __syncthreads();

            // GEMM: thread = cout pair {2ty, 2ty+1} x 8 spatial
            const int sbase = tx * 8;
            ull acc[8];
            {
                ull bp = pack2(b1[2 * ty], b1[2 * ty + 1]);
                #pragma unroll
                for (int j = 0; j < 8; j++) acc[j] = bp;
            }
            #pragma unroll 2
            for (int cin = 0; cin < CTOT; cin++) {
                ull wA = *(const ull*)&Ws1[cin * 64 + 2 * ty];
                const float4* xq = (const float4*)&Xs[cin * 264 + sbase];
                float4 xa = xq[0], xb = xq[1];
                ull xd[8];
                xd[0] = pack2(xa.x, xa.x); xd[1] = pack2(xa.y, xa.y);
                xd[2] = pack2(xa.z, xa.z); xd[3] = pack2(xa.w, xa.w);
                xd[4] = pack2(xb.x, xb.x); xd[5] = pack2(xb.y, xb.y);
                xd[6] = pack2(xb.z, xb.z); xd[7] = pack2(xb.w, xb.w);
                #pragma unroll
                for (int j = 0; j < 8; j++) acc[j] = fma2(wA, xd[j], acc[j]);
            }
            // outputs
            {
                float lo[8], hi[8];
                #pragma unroll
                for (int j = 0; j < 8; j++) unpack2(acc[j], lo[j], hi[j]);
                size_t r0 = ((size_t)b * HID + 2 * ty) * SPAT + s0 + sbase;
                size_t r1 = ((size_t)b * HID + 2 * ty + 1) * SPAT + s0 + sbase;
                *(float4*)&g_x1[r0]     = make_float4(lo[0], lo[1], lo[2], lo[3]);
                *(float4*)&g_x1[r0 + 4] = make_float4(lo[4], lo[5], lo[6], lo[7]);
                *(float4*)&g_x1[r1]     = make_float4(hi[0], hi[1], hi[2], hi[3]);
                *(float4*)&g_x1[r1 + 4] = make_float4(hi[4], hi[5], hi[6], hi[7]);
            }
            // packed stats over this thread's 8 spatial positions
            ull s = add2(add2(acc[0], acc[1]), add2(acc[2], acc[3]));
            s = add2(s, add2(add2(acc[4], acc[5]), add2(acc[6], acc[7])));
            ull q = mul2(acc[0], acc[0]);
            #pragma unroll
            for (int j = 1; j < 8; j++) q = fma2(acc[j], acc[j], q);
            __syncthreads();            // all Xs reads done -> reuse as staging
            ull* stgS = (ull*)Xs;       // 1024 entries
            ull* stgQ = stgS + 1024;    // 1024 entries (16 KB total, fits in Xs)
            stgS[t] = s;                // t = tx*32 + ty
            stgQ[t] = q;
            __syncthreads();
            if (t < 32) {
                ull ss = stgS[t], qq = stgQ[t];       // ww = 0
                #pragma unroll 4
                for (int ww = 1; ww < 32; ww++) {
                    ss = add2(ss, stgS[ww * 32 + t]);
                    qq = add2(qq, stgQ[ww * 32 + t]);
                }
                float sl, sh, ql, qh;
                unpack2(ss, sl, sh); unpack2(qq, ql, qh);
                int pi0 = ((b * HID + 2 * t) * NT1 + tb) * 2;
                int pi1 = ((b * HID + 2 * t + 1) * NT1 + tb) * 2;
                g_p1[pi0] = sl; g_p1[pi0 + 1] = ql;
                g_p1[pi1] = sh; g_p1[pi1 + 1] = qh;
            }
            __syncthreads();   // staging/Xs reuse safe for next tile
        }
    }
}

// ---------------- K1: fused FPS + kNN + conv1 (144 blocks, one wave) --------
__global__ void __launch_bounds__(1024, 1)
fused_fps_knn(const float* __restrict__ xyz, float* __restrict__ cent,
              const float* __restrict__ feat, const float* __restrict__ b1) {
    extern __shared__ float sm[];
    if (blockIdx.x < B_) fps_body(sm, xyz, cent, blockIdx.x);
    else                 knn_body(sm, xyz, cent, feat, b1, blockIdx.x - B_);
}

// ---------------- K4/K6: reduce stats partials ----------------
__global__ void __launch_bounds__(256)
stats1_kernel() {
    const int bid = blockIdx.x;                    // b*HID + c
    float s = 0.f, q = 0.f;
    for (int i = threadIdx.x; i < NT1; i += 256) {
        s += g_p1[(bid * NT1 + i) * 2];
        q += g_p1[(bid * NT1 + i) * 2 + 1];
    }
    float2 r = blk_reduce2(s, q);
    if (threadIdx.x == 0) { g_cs1[bid * 2] = r.x; g_cs1[bid * 2 + 1] = r.y; }
}

__global__ void __launch_bounds__(256)
stats2_kernel() {
    const int bid = blockIdx.x;                    // b*OUTC + c
    float s = 0.f, q = 0.f;
    for (int i = threadIdx.x; i < NBLK; i += 256) {
        s += g_p2[(bid * NBLK + i) * 2];
        q += g_p2[(bid * NBLK + i) * 2 + 1];
    }
    float2 r = blk_reduce2(s, q);
    if (threadIdx.x == 0) { g_cs2[bid * 2] = r.x; g_cs2[bid * 2 + 1] = r.y; }
}

// ---------------- K5: GN1+ReLU + conv2 (round-13 form: 128 thr, 64 sp) ------
__global__ void __launch_bounds__(128)
conv2_kernel(const float* __restrict__ b2,
             const float* __restrict__ g1w, const float* __restrict__ g1b) {
    extern __shared__ float dsm[];
    float* Ws = dsm;                           // [cin][128] 32 KB
    float* Hs = dsm + HID * OUTC;              // [cin][72]  18 KB
    float* sc = Hs + HID * 72;                 // 64
    float* sh = sc + HID;                      // 64
    __shared__ float4 pmm[4][64];
    __shared__ ull   psum[4][64];
    __shared__ ull   psq[4][64];
    const int b = blockIdx.y, bx = blockIdx.x, s0 = bx * 64, tid = threadIdx.x;
    const int warp = tid >> 5, lane = tid & 31;

    {
        const float4* src = (const float4*)g_w2t;
        float4* dst = (float4*)Ws;
        #pragma unroll
        for (int p = 0; p < 16; p++) dst[tid + p * 128] = src[tid + p * 128];
    }
    if (tid < HID) {
        int c = tid, g = c >> 1, cb = b * HID + g * 2;
        float sum = g_cs1[cb * 2]     + g_cs1[(cb + 1) * 2];
        float sq  = g_cs1[cb * 2 + 1] + g_cs1[(cb + 1) * 2 + 1];
        float inv = 1.0f / 65536.0f;
        float mu = sum * inv;
        float var = sq * inv - mu * mu;
        float a = rsqrtf(var + EPSV) * g1w[c];
        sc[c] = a;
        sh[c] = g1b[c] - mu * a;
    }
    __syncthreads();
    #pragma unroll
    for (int p = 0; p < 8; p++) {
        const int i = tid + p * 128;
        const int r = i >> 4, col = (i & 15) * 4;
        const float a = sc[r], o = sh[r];
        float4 v = *(const float4*)(g_x1 + ((size_t)b * HID + r) * SPAT + s0 + col);
        Hs[r * 72 + col + 0] = fmaxf(fmaf(v.x, a, o), 0.f);
        Hs[r * 72 + col + 1] = fmaxf(fmaf(v.y, a, o), 0.f);
        Hs[r * 72 + col + 2] = fmaxf(fmaf(v.z, a, o), 0.f);
        Hs[r * 72 + col + 3] = fmaxf(fmaf(v.w, a, o), 0.f);
    }
    __syncthreads();

    const int ty = tid & 15, tx = tid >> 4, sbase = tx * 8;
    ull acc[4][8];
    #pragma unroll
    for (int p = 0; p < 4; p++) {
        int c = 2 * ty + 32 * p;
        ull bp = pack2(b2[c], b2[c + 1]);
        #pragma unroll
        for (int j = 0; j < 8; j++) acc[p][j] = bp;
    }
    #pragma unroll 2
    for (int cin = 0; cin < HID; cin++) {
        const float* wrow = &Ws[cin * OUTC + 2 * ty];
        ull w0 = *(const ull*)(wrow);
        ull w1v = *(const ull*)(wrow + 32);
        ull w2v = *(const ull*)(wrow + 64);
        ull w3v = *(const ull*)(wrow + 96);
        const float4* xq = (const float4*)&Hs[cin * 72 + sbase];
        float4 xa = xq[0], xb = xq[1];
        ull xd[8];
        xd[0] = pack2(xa.x, xa.x); xd[1] = pack2(xa.y, xa.y);
        xd[2] = pack2(xa.z, xa.z); xd[3] = pack2(xa.w, xa.w);
        xd[4] = pack2(xb.x, xb.x); xd[5] = pack2(xb.y, xb.y);
        xd[6] = pack2(xb.z, xb.z); xd[7] = pack2(xb.w, xb.w);
        #pragma unroll
        for (int j = 0; j < 8; j++) {
            acc[0][j] = fma2(w0,  xd[j], acc[0][j]);
            acc[1][j] = fma2(w1v, xd[j], acc[1][j]);
            acc[2][j] = fma2(w2v, xd[j], acc[2][j]);
            acc[3][j] = fma2(w3v, xd[j], acc[3][j]);
        }
    }

    #pragma unroll
    for (int p = 0; p < 4; p++) {
        float lo[8], hi[8];
        #pragma unroll
        for (int j = 0; j < 8; j++) unpack2(acc[p][j], lo[j], hi[j]);
        float mxl = lo[0], mnl = lo[0], mxh = hi[0], mnh = hi[0];
        #pragma unroll
        for (int j = 1; j < 8; j++) {
            mxl = fmaxf(mxl, lo[j]); mnl = fminf(mnl, lo[j]);
            mxh = fmaxf(mxh, hi[j]); mnh = fminf(mnh, hi[j]);
        }
        mxl = fmaxf(mxl, __shfl_down_sync(FULLMASK, mxl, 16));
        mnl = fminf(mnl, __shfl_down_sync(FULLMASK, mnl, 16));
        mxh = fmaxf(mxh, __shfl_down_sync(FULLMASK, mxh, 16));
        mnh = fminf(mnh, __shfl_down_sync(FULLMASK, mnh, 16));
        ull s = add2(add2(acc[p][0], acc[p][1]), add2(acc[p][2], acc[p][3]));
        s = add2(s, add2(add2(acc[p][4], acc[p][5]), add2(acc[p][6], acc[p][7])));
        ull q = mul2(acc[p][0], acc[p][0]);
        #pragma unroll
        for (int j = 1; j < 8; j++) q = fma2(acc[p][j], acc[p][j], q);
        s = add2(s, __shfl_down_sync(FULLMASK, s, 16));
        q = add2(q, __shfl_down_sync(FULLMASK, q, 16));
        if (lane < 16) {
            pmm[warp][lane * 4 + p] = make_float4(mxl, mxh, mnl, mnh);
            psum[warp][lane * 4 + p] = s;
            psq[warp][lane * 4 + p] = q;
        }
    }
    __syncthreads();
    if (tid < 64) {
        const int i = tid, typ = i >> 2, pp = i & 3;
        const int cl = 2 * typ + 32 * pp, ch = cl + 1;
        const int m0i = s0 >> 5, m1i = m0i + 1;
        float4 a0 = pmm[0][i], a1 = pmm[1][i], a2 = pmm[2][i], a3 = pmm[3][i];
        size_t o0 = ((size_t)b * M_ + m0i) * OUTC;
        size_t o1 = ((size_t)b * M_ + m1i) * OUTC;
        g_mx2[o0 + cl] = fmaxf(a0.x, a1.x);  g_mx2[o0 + ch] = fmaxf(a0.y, a1.y);
        g_mn2[o0 + cl] = fminf(a0.z, a1.z);  g_mn2[o0 + ch] = fminf(a0.w, a1.w);
        g_mx2[o1 + cl] = fmaxf(a2.x, a3.x);  g_mx2[o1 + ch] = fmaxf(a2.y, a3.y);
        g_mn2[o1 + cl] = fminf(a2.z, a3.z);  g_mn2[o1 + ch] = fminf(a2.w, a3.w);
        ull s = add2(add2(psum[0][i], psum[1][i]), add2(psum[2][i], psum[3][i]));
        ull q = add2(add2(psq[0][i],  psq[1][i]),  add2(psq[2][i],  psq[3][i]));
        float sl, shv, ql, qh;
        unpack2(s, sl, shv); unpack2(q, ql, qh);
        int pi0 = ((b * OUTC + cl) * NBLK + bx) * 2;
        int pi1 = ((b * OUTC + ch) * NBLK + bx) * 2;
        g_p2[pi0] = sl; g_p2[pi0 + 1] = ql;
        g_p2[pi1] = shv; g_p2[pi1 + 1] = qh;
    }
}

// ---------------- K7: GN2 affine on max/min + progress reset ----------------
__global__ void __launch_bounds__(256)
final_kernel(const float* __restrict__ g2w, const float* __restrict__ g2b,
             float* __restrict__ out) {
    const int b = blockIdx.y;
    const int tid = threadIdx.x;
    if (blockIdx.x == 0 && b == 0 && tid < B_) g_prog[tid * 32] = 0;
    const int c = tid & 127;
    const int m = blockIdx.x * 2 + (tid >> 7);
    const int g = c >> 2, cb = b * OUTC + g * 4;
    float sum = 0.f, sq = 0.f;
    #pragma unroll
    for (int q = 0; q < 4; q++) {
        sum += g_cs2[(cb + q) * 2];
        sq  += g_cs2[(cb + q) * 2 + 1];
    }
    const float inv = 1.0f / 131072.0f;
    float mu = sum * inv;
    float var = sq * inv - mu * mu;
    float a = rsqrtf(var + EPSV) * g2w[c];
    float o = g2b[c] - mu * a;
    size_t off = ((size_t)b * M_ + m) * OUTC + c;
    float mx = g_mx2[off], mn = g_mn2[off];
    float v = (a >= 0.f) ? fmaf(mx, a, o) : fmaf(mn, a, o);
    out[off] = fmaxf(v, 0.f);
}

// ---------------- launch ----------------
extern "C" void kernel_launch(void* const* d_in, const int* in_sizes, int n_in,
                              void* d_out, int out_size) {
    const float* xyz  = (const float*)d_in[0];
    const float* feat = (const float*)d_in[1];
    const float* w1   = (const float*)d_in[2];
    const float* b1   = (const float*)d_in[3];
    const float* g1w  = (const float*)d_in[4];
    const float* g1b  = (const float*)d_in[5];
    const float* w2   = (const float*)d_in[6];
    const float* b2   = (const float*)d_in[7];
    const float* g2w  = (const float*)d_in[8];
    const float* g2b  = (const float*)d_in[9];

    float* out = (float*)d_out;
    float* cent;
    float* nf;
    if (out_size == B_ * M_ * 3 + B_ * M_ * OUTC) {
        cent = out;
        nf = out + (size_t)B_ * M_ * 3;
    } else {
        void* p = nullptr;
        cudaGetSymbolAddress(&p, g_centfb);
        cent = (float*)p;
        nf = out;
    }

    const int fsmem  = (4 * N_ + CTOT * 64 + CTOT * 264) * 4;   // ~214 KB
    const int c2smem = (HID * OUTC + HID * 72 + 2 * HID) * 4;   // ~50.5 KB
    cudaFuncSetAttribute(fused_fps_knn, cudaFuncAttributeMaxDynamicSharedMemorySize, fsmem);
    cudaFuncSetAttribute(conv2_kernel, cudaFuncAttributeMaxDynamicSharedMemorySize, c2smem);

    // launches: wprep(1), dummy(2), dummy(3), fused(4 <- ncu slot), stats1(5),
    //           conv2(6), stats2(7), final(8)
    wprep_kernel<<<64, 256>>>(w1, w2);
    dummy_kernel<<<1, 32>>>(1);
    dummy_kernel<<<1, 32>>>(2);
    fused_fps_knn<<<B_ + B_ * KNNB, 1024, fsmem>>>(xyz, cent, feat, b1);
    stats1_kernel<<<B_ * HID, 256>>>();
    conv2_kernel<<<dim3(NBLK, B_), 128, c2smem>>>(b2, g1w, g1b);
    stats2_kernel<<<B_ * OUTC, 256>>>();
    final_kernel<<<dim3(M_ / 2, B_), 256>>>(g2w, g2b, nf);
}

// round 16
// speedup vs baseline: 1.0795x; 1.0795x over previous
#include <cuda_runtime.h>
#include <cstdint>
#include <cstddef>

#define FULLMASK 0xffffffffu

#define B_   16
#define N_   8192
#define CIN  64
#define CTOT 67
#define M_   1024
#define KK   32
#define HID  64
#define OUTC 128
#define SPAT (M_*KK)
#define NBLK (SPAT/64)      // 512 conv2 tiles per batch
#define NT1  128            // conv1 tiles per batch (256 spatial each)
#define KNNB 8              // knn blocks per batch (16*8+16 = 144 blocks: ONE wave)
#define EPSV 1e-5f

typedef unsigned long long ull;

// ---------------- device scratch (static, no allocation) ----------------
__device__ int   g_knn[B_*M_*KK];                       // 2 MB
__device__ float g_x1[(size_t)B_*HID*SPAT];             // 134 MB
__device__ float g_p1[B_*HID*NT1*2];                    // 1 MB
__device__ float g_p2[B_*OUTC*NBLK*2];                  // 8 MB
__device__ float g_mx2[(size_t)B_*M_*OUTC];             // 8 MB
__device__ float g_mn2[(size_t)B_*M_*OUTC];             // 8 MB
__device__ float g_cs1[B_*HID*2];
__device__ float g_cs2[B_*OUTC*2];
__device__ float g_centfb[B_*M_*3];
__device__ unsigned g_prog[B_*32];                      // 128B-padded per batch
__device__ float g_w1t[CTOT*64];                        // transposed weights [cin][cout]
__device__ float g_w2t[HID*OUTC];

// ---------------- packed f32x2 helpers ----------------
__device__ __forceinline__ ull pack2(float lo, float hi) {
    ull r;
    asm("mov.b64 %0, {%1, %2};" : "=l"(r)
        : "r"(__float_as_uint(lo)), "r"(__float_as_uint(hi)));
    return r;
}
__device__ __forceinline__ void unpack2(ull v, float& lo, float& hi) {
    unsigned a, b;
    asm("mov.b64 {%0, %1}, %2;" : "=r"(a), "=r"(b) : "l"(v));
    lo = __uint_as_float(a); hi = __uint_as_float(b);
}
__device__ __forceinline__ ull add2(ull a, ull b) {
    ull r; asm("add.rn.f32x2 %0, %1, %2;" : "=l"(r) : "l"(a), "l"(b)); return r;
}
__device__ __forceinline__ ull mul2(ull a, ull b) {
    ull r; asm("mul.rn.f32x2 %0, %1, %2;" : "=l"(r) : "l"(a), "l"(b)); return r;
}
__device__ __forceinline__ ull fma2(ull a, ull b, ull c) {
    ull r; asm("fma.rn.f32x2 %0, %1, %2, %3;" : "=l"(r) : "l"(a), "l"(b), "l"(c)); return r;
}

// ---------------- reduction helpers ----------------
__device__ __forceinline__ unsigned redux_max_u32(unsigned v) {
    unsigned r;
    asm volatile("redux.sync.max.u32 %0, %1, 0xffffffff;" : "=r"(r) : "r"(v));
    return r;
}
__device__ __forceinline__ unsigned redux_min_u32(unsigned v) {
    unsigned r;
    asm volatile("redux.sync.min.u32 %0, %1, 0xffffffff;" : "=r"(r) : "r"(v));
    return r;
}
__device__ __forceinline__ int redux_max_s32(int v) {
    int r;
    asm volatile("redux.sync.max.s32 %0, %1, 0xffffffff;" : "=r"(r) : "r"(v));
    return r;
}

__device__ __forceinline__ unsigned f2key(float f) {
    unsigned u = __float_as_uint(f);
    unsigned mask = ((unsigned)((int)u >> 31)) | 0x80000000u;
    return u ^ mask;
}

__device__ __forceinline__ float2 blk_reduce2(float s, float s2) {
    const int lane = threadIdx.x & 31, w = threadIdx.x >> 5;
    #pragma unroll
    for (int o = 16; o; o >>= 1) {
        s  += __shfl_down_sync(FULLMASK, s,  o);
        s2 += __shfl_down_sync(FULLMASK, s2, o);
    }
    __shared__ float rs[8], rq[8];
    if (lane == 0) { rs[w] = s; rq[w] = s2; }
    __syncthreads();
    if (w == 0) {
        s  = (lane < 8) ? rs[lane] : 0.f;
        s2 = (lane < 8) ? rq[lane] : 0.f;
        #pragma unroll
        for (int o = 4; o; o >>= 1) {
            s  += __shfl_down_sync(FULLMASK, s,  o);
            s2 += __shfl_down_sync(FULLMASK, s2, o);
        }
    }
    return make_float2(s, s2);
}

// ---------------- progress handshake (padded counters + backoff) ------------
__device__ __forceinline__ void publish_prog(int b, unsigned v) {
    asm volatile("st.release.gpu.global.u32 [%0], %1;"
                 :: "l"(&g_prog[b * 32]), "r"(v) : "memory");
}
__device__ __forceinline__ void wait_prog(int b, unsigned need) {
    const int lane = threadIdx.x & 31;
    if (lane == 0) {
        unsigned got;
        for (;;) {
            asm volatile("ld.acquire.gpu.global.u32 %0, [%1];"
                         : "=r"(got) : "l"(&g_prog[b * 32]) : "memory");
            if (got >= need) break;
            __nanosleep((need - got > 16) ? 4000 : 300);
        }
    }
    __syncwarp();
}

// ---------------- K0: weight transpose prep ----------------
__global__ void wprep_kernel(const float* __restrict__ w1,
                             const float* __restrict__ w2) {
    const int t = blockIdx.x * 256 + threadIdx.x;
    if (t < CTOT * 64) {
        int cin = t >> 6, c = t & 63;
        g_w1t[cin * 64 + c] = w1[c * CTOT + cin];
    }
    if (t < HID * OUTC) {
        int cin = t >> 7, c = t & 127;
        g_w2t[cin * OUTC + c] = w2[c * HID + cin];
    }
}

// ---------------- FPS body (blocks 0..15): 512 thr, 16 pts/thread -----------
__device__ __forceinline__ void fps_body(float* sm, const float* __restrict__ xyz,
                                         float* __restrict__ cent, int b) {
    float* xs = sm; float* ys = sm + N_; float* zs = sm + 2 * N_;
    __shared__ unsigned swb[2][16];
    __shared__ unsigned swi[2][16];
    const int t = threadIdx.x, lane = t & 31, w = t >> 5;
    const float* base = xyz + (size_t)b * N_ * 3;
    for (int p = t; p < N_; p += 512) {
        xs[p] = base[3 * p]; ys[p] = base[3 * p + 1]; zs[p] = base[3 * p + 2];
    }
    __syncthreads();

    ull px2[8], py2[8], pz2[8];
    float dist[16];
    #pragma unroll
    for (int j = 0; j < 8; j++) {
        const int p0 = t + (2 * j) * 512, p1 = p0 + 512;
        px2[j] = pack2(xs[p0], xs[p1]);
        py2[j] = pack2(ys[p0], ys[p1]);
        pz2[j] = pack2(zs[p0], zs[p1]);
        dist[2 * j] = 1e10f; dist[2 * j + 1] = 1e10f;
    }
    float cx = xs[0], cy = ys[0], cz = zs[0];
    if (t == 0) {
        size_t o = (size_t)b * M_ * 3;
        cent[o] = cx; cent[o + 1] = cy; cent[o + 2] = cz;
        publish_prog(b, 1u);
    }

    for (int it = 1; it < M_; ++it) {
        const ull ncx = pack2(-cx, -cx);   // p + (-c) == p - c exactly (IEEE)
        const ull ncy = pack2(-cy, -cy);
        const ull ncz = pack2(-cz, -cz);
        float mv = -1.f;
        #pragma unroll
        for (int j = 0; j < 8; j++) {
            ull dx = add2(px2[j], ncx);
            ull dy = add2(py2[j], ncy);
            ull dz = add2(pz2[j], ncz);
            ull d = add2(add2(mul2(dx, dx), mul2(dy, dy)), mul2(dz, dz));
            float d0, d1; unpack2(d, d0, d1);
            float n0 = fminf(dist[2 * j], d0);
            float n1 = fminf(dist[2 * j + 1], d1);
            dist[2 * j] = n0; dist[2 * j + 1] = n1;
            mv = fmaxf(mv, fmaxf(n0, n1));
        }
        unsigned mi = 0;
        #pragma unroll
        for (int k = 15; k >= 0; k--)
            if (dist[k] == mv) mi = (unsigned)(t + k * 512);

        unsigned mb = __float_as_uint(mv);
        unsigned wm = redux_max_u32(mb);
        unsigned wi = redux_min_u32((mb == wm) ? mi : 0xFFFFFFFFu);
        const int pb = it & 1;
        if (lane == 0) { swb[pb][w] = wm; swi[pb][w] = wi; }
        __syncthreads();
        unsigned vb = (lane < 16) ? swb[pb][lane] : 0u;
        unsigned vi = (lane < 16) ? swi[pb][lane] : 0xFFFFFFFFu;
        unsigned gm = redux_max_u32(vb);
        unsigned far = redux_min_u32((vb == gm) ? vi : 0xFFFFFFFFu);
        cx = xs[far]; cy = ys[far]; cz = zs[far];
        if (t == 0) {
            size_t o = ((size_t)b * M_ + it) * 3;
            cent[o] = cx; cent[o + 1] = cy; cent[o + 2] = cz;
            publish_prog(b, (unsigned)(it + 1));
        }
    }
}

// ---------------- kNN + conv1 body (blocks 16..143): 512 thr ----------------
// Warp wg = cb*16 + w scans mi = wg + 128*i (frontier-tracking); after a block
// barrier, the block runs conv1 for its 16 fresh m's as 2 tiles of 8 m.
__device__ __forceinline__ void knn_body(float* sm, const float* __restrict__ xyz,
                                         const float* __restrict__ cent,
                                         const float* __restrict__ feat,
                                         const float* __restrict__ b1, int idx) {
    float* xs = sm; float* ys = sm + N_; float* zs = sm + 2 * N_; float* xn = sm + 3 * N_;
    float* Ws1 = sm + 4 * N_;                  // CTOT*64 floats
    float* Xs  = Ws1 + CTOT * 64;              // CTOT*264 floats
    __shared__ float scent[16][4];
    __shared__ ull stgSA[16][16], stgQA[16][16], stgSB[16][16], stgQB[16][16];
    const int b = idx >> 3, cb = idx & 7;
    const int t = threadIdx.x, lane = t & 31, w = t >> 5;
    const int wg = cb * 16 + w;                 // 0..127
    const float* base = xyz + (size_t)b * N_ * 3;
    for (int p = t; p < N_; p += 512) {
        float x = base[3 * p], y = base[3 * p + 1], z = base[3 * p + 2];
        xs[p] = x; ys[p] = y; zs[p] = z;
        xn[p] = x * x + y * y + z * z;
    }
    for (int i = t; i < CTOT * 64; i += 512) Ws1[i] = g_w1t[i];
    __syncthreads();

    const int ty = t & 15, tx = t >> 4;          // GEMM mapping
    for (int i = 0; i < 8; ++i) {
        // ---- scan phase: each warp one centroid ----
        const int mi = wg + 128 * i;
        wait_prog(b, (unsigned)(mi + 1));
        size_t co = ((size_t)b * M_ + mi) * 3;
        float cx = __ldcg(cent + co);
        float cy = __ldcg(cent + co + 1);
        float cz = __ldcg(cent + co + 2);
        if (lane == 0) { scent[w][0] = cx; scent[w][1] = cy; scent[w][2] = cz; }
        float cn = cx * cx + cy * cy + cz * cz;

        unsigned valkey; int vidx;
        {
            int p = lane;
            float d = cn + xn[p] - 2.f * (cx * xs[p] + cy * ys[p] + cz * zs[p]);
            valkey = f2key(d);
            vidx = p;
        }
        unsigned thr = redux_max_u32(valkey);
        for (int c0 = 32; c0 < N_; c0 += 32) {
            int p = c0 + lane;
            float d = cn + xn[p] - 2.f * (cx * xs[p] + cy * ys[p] + cz * zs[p]);
            unsigned dk = f2key(d);
            unsigned pend = __ballot_sync(FULLMASK, dk < thr);
            while (pend) {
                int src = __ffs(pend) - 1;
                pend &= pend - 1;
                unsigned dkj = __shfl_sync(FULLMASK, dk, src);
                if (dkj < thr) {
                    int pj = c0 + src;
                    unsigned vmax = redux_max_u32(valkey);
                    int cand = (valkey == vmax) ? vidx : -1;
                    int victimidx = redux_max_s32(cand);
                    if (valkey == vmax && vidx == victimidx) { valkey = dkj; vidx = pj; }
                    thr = redux_max_u32(valkey);
                }
            }
        }
        g_knn[((size_t)b * M_ + mi) * KK + lane] = vidx;
        __syncthreads();    // all 16 warps done; knn + scent visible block-wide

        // ---- conv1 phase: 2 tiles of 8 m (256 spatial) ----
        const int mbase = cb * 16 + 128 * i;
        #pragma unroll 1
        for (int tt = 0; tt < 2; tt++) {
            const int m0 = mbase + tt * 8;
            const int tb = m0 >> 3;              // tile index 0..127
            const int s0 = m0 * KK;
            {   // gather: 2 threads per point
                const int r = t & 1, ps = t >> 1;
                const int s = s0 + ps, m = s >> 5, kk = s & 31;
                const int gidx = g_knn[((size_t)b * M_ + m) * KK + kk];
                const float* fp = feat + ((size_t)b * N_ + gidx) * CIN + r * 32;
                #pragma unroll
                for (int q = 0; q < 8; q++) {
                    float4 v = *(const float4*)(fp + q * 4);
                    int row = 3 + r * 32 + q * 4;
                    Xs[(row + 0) * 264 + ps] = v.x;
                    Xs[(row + 1) * 264 + ps] = v.y;
                    Xs[(row + 2) * 264 + ps] = v.z;
                    Xs[(row + 3) * 264 + ps] = v.w;
                }
                if (r == 0) {
                    const int lw = m - mbase;
                    Xs[0 * 264 + ps] = xs[gidx] - scent[lw][0];
                    Xs[1 * 264 + ps] = ys[gidx] - scent[lw][1];
                    Xs[2 * 264 + ps] = zs[gidx] - scent[lw][2];
                }
            }
            __syncthreads();

            const int sbase = tx * 8;
            ull accA[8], accB[8];
            {
                ull bA = pack2(b1[2 * ty], b1[2 * ty + 1]);
                ull bB = pack2(b1[2 * ty + 32], b1[2 * ty + 33]);
                #pragma unroll
                for (int j = 0; j < 8; j++) { accA[j] = bA; accB[j] = bB; }
            }
            #pragma unroll 2
            for (int cin = 0; cin < CTOT; cin++) {
                ull wA = *(const ull*)&Ws1[cin * 64 + 2 * ty];
                ull wB = *(const ull*)&Ws1[cin * 64 + 2 * ty + 32];
                const float4* xq = (const float4*)&Xs[cin * 264 + sbase];
                float4 xa = xq[0], xb = xq[1];
                ull xd[8];
                xd[0] = pack2(xa.x, xa.x); xd[1] = pack2(xa.y, xa.y);
                xd[2] = pack2(xa.z, xa.z); xd[3] = pack2(xa.w, xa.w);
                xd[4] = pack2(xb.x, xb.x); xd[5] = pack2(xb.y, xb.y);
                xd[6] = pack2(xb.z, xb.z); xd[7] = pack2(xb.w, xb.w);
                #pragma unroll
                for (int j = 0; j < 8; j++) {
                    accA[j] = fma2(wA, xd[j], accA[j]);
                    accB[j] = fma2(wB, xd[j], accB[j]);
                }
            }
            {
                float lo[8], hi[8];
                #pragma unroll
                for (int j = 0; j < 8; j++) unpack2(accA[j], lo[j], hi[j]);
                size_t r0 = ((size_t)b * HID + 2 * ty) * SPAT + s0 + sbase;
                size_t r1 = ((size_t)b * HID + 2 * ty + 1) * SPAT + s0 + sbase;
                *(float4*)&g_x1[r0]     = make_float4(lo[0], lo[1], lo[2], lo[3]);
                *(float4*)&g_x1[r0 + 4] = make_float4(lo[4], lo[5], lo[6], lo[7]);
                *(float4*)&g_x1[r1]     = make_float4(hi[0], hi[1], hi[2], hi[3]);
                *(float4*)&g_x1[r1 + 4] = make_float4(hi[4], hi[5], hi[6], hi[7]);
                #pragma unroll
                for (int j = 0; j < 8; j++) unpack2(accB[j], lo[j], hi[j]);
                size_t r2 = ((size_t)b * HID + 2 * ty + 32) * SPAT + s0 + sbase;
                size_t r3 = ((size_t)b * HID + 2 * ty + 33) * SPAT + s0 + sbase;
                *(float4*)&g_x1[r2]     = make_float4(lo[0], lo[1], lo[2], lo[3]);
                *(float4*)&g_x1[r2 + 4] = make_float4(lo[4], lo[5], lo[6], lo[7]);
                *(float4*)&g_x1[r3]     = make_float4(hi[0], hi[1], hi[2], hi[3]);
                *(float4*)&g_x1[r3 + 4] = make_float4(hi[4], hi[5], hi[6], hi[7]);
            }
            {
                ull sA = add2(add2(accA[0], accA[1]), add2(accA[2], accA[3]));
                sA = add2(sA, add2(add2(accA[4], accA[5]), add2(accA[6], accA[7])));
                ull qA = mul2(accA[0], accA[0]);
                #pragma unroll
                for (int j = 1; j < 8; j++) qA = fma2(accA[j], accA[j], qA);
                ull sB = add2(add2(accB[0], accB[1]), add2(accB[2], accB[3]));
                sB = add2(sB, add2(add2(accB[4], accB[5]), add2(accB[6], accB[7])));
                ull qB = mul2(accB[0], accB[0]);
                #pragma unroll
                for (int j = 1; j < 8; j++) qB = fma2(accB[j], accB[j], qB);
                sA = add2(sA, __shfl_down_sync(FULLMASK, sA, 16));
                qA = add2(qA, __shfl_down_sync(FULLMASK, qA, 16));
                sB = add2(sB, __shfl_down_sync(FULLMASK, sB, 16));
                qB = add2(qB, __shfl_down_sync(FULLMASK, qB, 16));
                if (lane < 16) {
                    stgSA[w][lane] = sA; stgQA[w][lane] = qA;
                    stgSB[w][lane] = sB; stgQB[w][lane] = qB;
                }
            }
            __syncthreads();
            if (t < 32) {
                const int tyy = t & 15;
                const int c = (t < 16) ? (2 * tyy) : (2 * tyy + 32);
                ull s = 0, q = 0;
                if (t < 16) {
                    s = stgSA[0][tyy]; q = stgQA[0][tyy];
                    #pragma unroll
                    for (int ww = 1; ww < 16; ww++) {
                        s = add2(s, stgSA[ww][tyy]); q = add2(q, stgQA[ww][tyy]);
                    }
                } else {
                    s = stgSB[0][tyy]; q = stgQB[0][tyy];
                    #pragma unroll
                    for (int ww = 1; ww < 16; ww++) {
                        s = add2(s, stgSB[ww][tyy]); q = add2(q, stgQB[ww][tyy]);
                    }
                }
                float sl, sh, ql, qh;
                unpack2(s, sl, sh); unpack2(q, ql, qh);
                int pi0 = ((b * HID + c) * NT1 + tb) * 2;
                int pi1 = ((b * HID + c + 1) * NT1 + tb) * 2;
                g_p1[pi0] = sl; g_p1[pi0 + 1] = ql;
                g_p1[pi1] = sh; g_p1[pi1 + 1] = qh;
            }
            __syncthreads();
        }
    }
}

// ---------------- K1: fused FPS + kNN + conv1 (144 blocks, one wave) --------
__global__ void __launch_bounds__(512, 1)
fused_fps_knn(const float* __restrict__ xyz, float* __restrict__ cent,
              const float* __restrict__ feat, const float* __restrict__ b1) {
    extern __shared__ float sm[];
    if (blockIdx.x < B_) fps_body(sm, xyz, cent, blockIdx.x);
    else                 knn_body(sm, xyz, cent, feat, b1, blockIdx.x - B_);
}

// ---------------- K4/K6: reduce stats partials ----------------
__global__ void __launch_bounds__(256)
stats1_kernel() {
    const int bid = blockIdx.x;                    // b*HID + c
    float s = 0.f, q = 0.f;
    for (int i = threadIdx.x; i < NT1; i += 256) {
        s += g_p1[(bid * NT1 + i) * 2];
        q += g_p1[(bid * NT1 + i) * 2 + 1];
    }
    float2 r = blk_reduce2(s, q);
    if (threadIdx.x == 0) { g_cs1[bid * 2] = r.x; g_cs1[bid * 2 + 1] = r.y; }
}

__global__ void __launch_bounds__(256)
stats2_kernel() {
    const int bid = blockIdx.x;                    // b*OUTC + c
    float s = 0.f, q = 0.f;
    for (int i = threadIdx.x; i < NBLK; i += 256) {
        s += g_p2[(bid * NBLK + i) * 2];
        q += g_p2[(bid * NBLK + i) * 2 + 1];
    }
    float2 r = blk_reduce2(s, q);
    if (threadIdx.x == 0) { g_cs2[bid * 2] = r.x; g_cs2[bid * 2 + 1] = r.y; }
}

// ---------------- K5: GN1+ReLU + conv2 (128 thr, 128cout x 64sp) ------------
__global__ void __launch_bounds__(128)
conv2_kernel(const float* __restrict__ b2,
             const float* __restrict__ g1w, const float* __restrict__ g1b) {
    extern __shared__ float dsm[];
    float* Ws = dsm;                           // [cin][128] 32 KB
    float* Hs = dsm + HID * OUTC;              // [cin][72]  18 KB
    float* sc = Hs + HID * 72;                 // 64
    float* sh = sc + HID;                      // 64
    __shared__ float4 pmm[4][64];
    __shared__ ull   psum[4][64];
    __shared__ ull   psq[4][64];
    const int b = blockIdx.y, bx = blockIdx.x, s0 = bx * 64, tid = threadIdx.x;
    const int warp = tid >> 5, lane = tid & 31;

    {
        const float4* src = (const float4*)g_w2t;
        float4* dst = (float4*)Ws;
        #pragma unroll
        for (int p = 0; p < 16; p++) dst[tid + p * 128] = src[tid + p * 128];
    }
    if (tid < HID) {
        int c = tid, g = c >> 1, cb = b * HID + g * 2;
        float sum = g_cs1[cb * 2]     + g_cs1[(cb + 1) * 2];
        float sq  = g_cs1[cb * 2 + 1] + g_cs1[(cb + 1) * 2 + 1];
        float inv = 1.0f / 65536.0f;
        float mu = sum * inv;
        float var = sq * inv - mu * mu;
        float a = rsqrtf(var + EPSV) * g1w[c];
        sc[c] = a;
        sh[c] = g1b[c] - mu * a;
    }
    __syncthreads();
    #pragma unroll
    for (int p = 0; p < 8; p++) {
        const int i = tid + p * 128;
        const int r = i >> 4, col = (i & 15) * 4;
        const float a = sc[r], o = sh[r];
        float4 v = *(const float4*)(g_x1 + ((size_t)b * HID + r) * SPAT + s0 + col);
        Hs[r * 72 + col + 0] = fmaxf(fmaf(v.x, a, o), 0.f);
        Hs[r * 72 + col + 1] = fmaxf(fmaf(v.y, a, o), 0.f);
        Hs[r * 72 + col + 2] = fmaxf(fmaf(v.z, a, o), 0.f);
        Hs[r * 72 + col + 3] = fmaxf(fmaf(v.w, a, o), 0.f);
    }
    __syncthreads();

    const int ty = tid & 15, tx = tid >> 4, sbase = tx * 8;
    ull acc[4][8];
    #pragma unroll
    for (int p = 0; p < 4; p++) {
        int c = 2 * ty + 32 * p;
        ull bp = pack2(b2[c], b2[c + 1]);
        #pragma unroll
        for (int j = 0; j < 8; j++) acc[p][j] = bp;
    }
    #pragma unroll 2
    for (int cin = 0; cin < HID; cin++) {
        const float* wrow = &Ws[cin * OUTC + 2 * ty];
        ull w0 = *(const ull*)(wrow);
        ull w1v = *(const ull*)(wrow + 32);
        ull w2v = *(const ull*)(wrow + 64);
        ull w3v = *(const ull*)(wrow + 96);
        const float4* xq = (const float4*)&Hs[cin * 72 + sbase];
        float4 xa = xq[0], xb = xq[1];
        ull xd[8];
        xd[0] = pack2(xa.x, xa.x); xd[1] = pack2(xa.y, xa.y);
        xd[2] = pack2(xa.z, xa.z); xd[3] = pack2(xa.w, xa.w);
        xd[4] = pack2(xb.x, xb.x); xd[5] = pack2(xb.y, xb.y);
        xd[6] = pack2(xb.z, xb.z); xd[7] = pack2(xb.w, xb.w);
        #pragma unroll
        for (int j = 0; j < 8; j++) {
            acc[0][j] = fma2(w0,  xd[j], acc[0][j]);
            acc[1][j] = fma2(w1v, xd[j], acc[1][j]);
            acc[2][j] = fma2(w2v, xd[j], acc[2][j]);
            acc[3][j] = fma2(w3v, xd[j], acc[3][j]);
        }
    }

    #pragma unroll
    for (int p = 0; p < 4; p++) {
        float lo[8], hi[8];
        #pragma unroll
        for (int j = 0; j < 8; j++) unpack2(acc[p][j], lo[j], hi[j]);
        float mxl = lo[0], mnl = lo[0], mxh = hi[0], mnh = hi[0];
        #pragma unroll
        for (int j = 1; j < 8; j++) {
            mxl = fmaxf(mxl, lo[j]); mnl = fminf(mnl, lo[j]);
            mxh = fmaxf(mxh, hi[j]); mnh = fminf(mnh, hi[j]);
        }
        mxl = fmaxf(mxl, __shfl_down_sync(FULLMASK, mxl, 16));
        mnl = fminf(mnl, __shfl_down_sync(FULLMASK, mnl, 16));
        mxh = fmaxf(mxh, __shfl_down_sync(FULLMASK, mxh, 16));
        mnh = fminf(mnh, __shfl_down_sync(FULLMASK, mnh, 16));
        ull s = add2(add2(acc[p][0], acc[p][1]), add2(acc[p][2], acc[p][3]));
        s = add2(s, add2(add2(acc[p][4], acc[p][5]), add2(acc[p][6], acc[p][7])));
        ull q = mul2(acc[p][0], acc[p][0]);
        #pragma unroll
        for (int j = 1; j < 8; j++) q = fma2(acc[p][j], acc[p][j], q);
        s = add2(s, __shfl_down_sync(FULLMASK, s, 16));
        q = add2(q, __shfl_down_sync(FULLMASK, q, 16));
        if (lane < 16) {
            pmm[warp][lane * 4 + p] = make_float4(mxl, mxh, mnl, mnh);
            psum[warp][lane * 4 + p] = s;
            psq[warp][lane * 4 + p] = q;
        }
    }
    __syncthreads();
    if (tid < 64) {
        const int i = tid, typ = i >> 2, pp = i & 3;
        const int cl = 2 * typ + 32 * pp, ch = cl + 1;
        const int m0i = s0 >> 5, m1i = m0i + 1;
        float4 a0 = pmm[0][i], a1 = pmm[1][i], a2 = pmm[2][i], a3 = pmm[3][i];
        size_t o0 = ((size_t)b * M_ + m0i) * OUTC;
        size_t o1 = ((size_t)b * M_ + m1i) * OUTC;
        g_mx2[o0 + cl] = fmaxf(a0.x, a1.x);  g_mx2[o0 + ch] = fmaxf(a0.y, a1.y);
        g_mn2[o0 + cl] = fminf(a0.z, a1.z);  g_mn2[o0 + ch] = fminf(a0.w, a1.w);
        g_mx2[o1 + cl] = fmaxf(a2.x, a3.x);  g_mx2[o1 + ch] = fmaxf(a2.y, a3.y);
        g_mn2[o1 + cl] = fminf(a2.z, a3.z);  g_mn2[o1 + ch] = fminf(a2.w, a3.w);
        ull s = add2(add2(psum[0][i], psum[1][i]), add2(psum[2][i], psum[3][i]));
        ull q = add2(add2(psq[0][i],  psq[1][i]),  add2(psq[2][i],  psq[3][i]));
        float sl, shv, ql, qh;
        unpack2(s, sl, shv); unpack2(q, ql, qh);
        int pi0 = ((b * OUTC + cl) * NBLK + bx) * 2;
        int pi1 = ((b * OUTC + ch) * NBLK + bx) * 2;
        g_p2[pi0] = sl; g_p2[pi0 + 1] = ql;
        g_p2[pi1] = shv; g_p2[pi1 + 1] = qh;
    }
}

// ---------------- K7: GN2 affine on max/min + progress reset ----------------
__global__ void __launch_bounds__(256)
final_kernel(const float* __restrict__ g2w, const float* __restrict__ g2b,
             float* __restrict__ out) {
    const int b = blockIdx.y;
    const int tid = threadIdx.x;
    if (blockIdx.x == 0 && b == 0 && tid < B_) g_prog[tid * 32] = 0;
    const int c = tid & 127;
    const int m = blockIdx.x * 2 + (tid >> 7);
    const int g = c >> 2, cb = b * OUTC + g * 4;
    float sum = 0.f, sq = 0.f;
    #pragma unroll
    for (int q = 0; q < 4; q++) {
        sum += g_cs2[(cb + q) * 2];
        sq  += g_cs2[(cb + q) * 2 + 1];
    }
    const float inv = 1.0f / 131072.0f;
    float mu = sum * inv;
    float var = sq * inv - mu * mu;
    float a = rsqrtf(var + EPSV) * g2w[c];
    float o = g2b[c] - mu * a;
    size_t off = ((size_t)b * M_ + m) * OUTC + c;
    float mx = g_mx2[off], mn = g_mn2[off];
    float v = (a >= 0.f) ? fmaf(mx, a, o) : fmaf(mn, a, o);
    out[off] = fmaxf(v, 0.f);
}

// ---------------- launch ----------------
extern "C" void kernel_launch(void* const* d_in, const int* in_sizes, int n_in,
                              void* d_out, int out_size) {
    const float* xyz  = (const float*)d_in[0];
    const float* feat = (const float*)d_in[1];
    const float* w1   = (const float*)d_in[2];
    const float* b1   = (const float*)d_in[3];
    const float* g1w  = (const float*)d_in[4];
    const float* g1b  = (const float*)d_in[5];
    const float* w2   = (const float*)d_in[6];
    const float* b2   = (const float*)d_in[7];
    const float* g2w  = (const float*)d_in[8];
    const float* g2b  = (const float*)d_in[9];

    float* out = (float*)d_out;
    float* cent;
    float* nf;
    if (out_size == B_ * M_ * 3 + B_ * M_ * OUTC) {
        cent = out;
        nf = out + (size_t)B_ * M_ * 3;
    } else {
        void* p = nullptr;
        cudaGetSymbolAddress(&p, g_centfb);
        cent = (float*)p;
        nf = out;
    }

    const int fsmem  = (4 * N_ + CTOT * 64 + CTOT * 264) * 4;   // ~214 KB
    const int c2smem = (HID * OUTC + HID * 72 + 2 * HID) * 4;   // ~50.5 KB
    cudaFuncSetAttribute(fused_fps_knn, cudaFuncAttributeMaxDynamicSharedMemorySize, fsmem);
    cudaFuncSetAttribute(conv2_kernel, cudaFuncAttributeMaxDynamicSharedMemorySize, c2smem);

    // launches: wprep(1), fused(2), stats1(3), conv2(4 <- ncu slot),
    //           stats2(5), final(6)
    wprep_kernel<<<64, 256>>>(w1, w2);
    fused_fps_knn<<<B_ + B_ * KNNB, 512, fsmem>>>(xyz, cent, feat, b1);
    stats1_kernel<<<B_ * HID, 256>>>();
    conv2_kernel<<<dim3(NBLK, B_), 128, c2smem>>>(b2, g1w, g1b);
    stats2_kernel<<<B_ * OUTC, 256>>>();
    final_kernel<<<dim3(M_ / 2, B_), 256>>>(g2w, g2b, nf);
}